// round 6
// baseline (speedup 1.0000x reference)
#include <cuda_runtime.h>
#include <math.h>

#define BB 64
#define NN 8192
#define WW 64
#define HH 4
#define CTRL 792   // H*(3W+6)
#define CB  8      // batches per chunk
#define NC  (BB/CB)

// ---------------- scratch (no allocation allowed) ----------------
__device__ float g_keys [BB*HH*WW];   // tanh(keys)
__device__ float g_erase[BB*HH*WW];   // sigmoid(erase)
__device__ float g_wvec [BB*HH*WW];   // tanh(write)
__device__ float g_params[BB*HH*8];   // beta,gate,s0,s1,s2,gamma,keynorm
__device__ float g_scores[(size_t)BB*HH*NN];  // beta * cosine
__device__ float g_w     [(size_t)BB*HH*NN];  // final write distribution

__device__ __forceinline__ float softplusf(float x){
    return x > 20.f ? x : log1pf(expf(x));
}
__device__ __forceinline__ float sigmoidf(float x){
    return 1.f/(1.f + expf(-x));
}

// ---------------- k0: control transforms (tiny) ----------------
__global__ void k0_controls(const float* __restrict__ ctrl){
    int bh = blockIdx.x;                 // b*4+h
    int b  = bh >> 2, h = bh & 3;
    int t  = threadIdx.x;                // 64 threads
    const float* c = ctrl + b*CTRL;

    float k = tanhf(c[h*WW + t]);
    g_keys [bh*WW + t] = k;
    g_erase[bh*WW + t] = sigmoidf(c[256 + h*WW + t]);
    g_wvec [bh*WW + t] = tanhf(c[512 + h*WW + t]);

    __shared__ float s2[2];
    float sq = k*k;
    #pragma unroll
    for (int o = 16; o; o >>= 1) sq += __shfl_xor_sync(0xffffffffu, sq, o);
    if ((t & 31) == 0) s2[t >> 5] = sq;
    __syncthreads();
    if (t == 0){
        float nrm   = sqrtf(s2[0] + s2[1]);
        float beta  = softplusf(c[768 + h]);
        float gate  = sigmoidf(c[772 + h]);
        float gamma = 1.f + softplusf(c[788 + h]);
        float a0 = c[776 + h*3 + 0], a1 = c[776 + h*3 + 1], a2 = c[776 + h*3 + 2];
        float m  = fmaxf(a0, fmaxf(a1, a2));
        float e0 = expf(a0 - m), e1 = expf(a1 - m), e2 = expf(a2 - m);
        float inv = 1.f/(e0 + e1 + e2);
        float* p = g_params + bh*8;
        p[0]=beta; p[1]=gate; p[2]=e0*inv; p[3]=e1*inv; p[4]=e2*inv; p[5]=gamma; p[6]=nrm;
    }
}

// ---------------- k1: beta * cosine scores (chunked over batch) ----------------
// 4 lanes per memory row, 16 floats (4 float4) per lane, 2 shuffle rounds.
#define K1_ROWSPB 64
__global__ __launch_bounds__(256) void k1_scores(const float* __restrict__ mem, int b0){
    int b  = b0 + blockIdx.y;
    int n0 = blockIdx.x * K1_ROWSPB;
    __shared__ float skey[HH*WW];
    __shared__ float sb[HH], skn[HH];
    int t = threadIdx.x;
    skey[t] = g_keys[b*HH*WW + t];
    if (t < HH){ sb[t] = g_params[(b*HH + t)*8 + 0]; skn[t] = g_params[(b*HH + t)*8 + 6]; }
    __syncthreads();

    int seg = t & 3;            // which 16-float segment of W
    int row = n0 + (t >> 2);    // one memory row per thread

    const float4* mrow = (const float4*)(mem + ((size_t)b*NN + row)*WW) + seg*4;
    float4 m0 = mrow[0], m1 = mrow[1], m2 = mrow[2], m3 = mrow[3];

    float sq = m0.x*m0.x + m0.y*m0.y + m0.z*m0.z + m0.w*m0.w
             + m1.x*m1.x + m1.y*m1.y + m1.z*m1.z + m1.w*m1.w
             + m2.x*m2.x + m2.y*m2.y + m2.z*m2.z + m2.w*m2.w
             + m3.x*m3.x + m3.y*m3.y + m3.z*m3.z + m3.w*m3.w;

    float d[HH];
    #pragma unroll
    for (int h = 0; h < HH; h++){
        const float4* kp = (const float4*)(skey + h*WW) + seg*4;
        float4 k0 = kp[0], k1 = kp[1], k2 = kp[2], k3 = kp[3];
        d[h] = m0.x*k0.x + m0.y*k0.y + m0.z*k0.z + m0.w*k0.w
             + m1.x*k1.x + m1.y*k1.y + m1.z*k1.z + m1.w*k1.w
             + m2.x*k2.x + m2.y*k2.y + m2.z*k2.z + m2.w*k2.w
             + m3.x*k3.x + m3.y*k3.y + m3.z*k3.z + m3.w*k3.w;
    }

    #pragma unroll
    for (int o = 1; o <= 2; o <<= 1){
        sq   += __shfl_xor_sync(0xffffffffu, sq,   o);
        d[0] += __shfl_xor_sync(0xffffffffu, d[0], o);
        d[1] += __shfl_xor_sync(0xffffffffu, d[1], o);
        d[2] += __shfl_xor_sync(0xffffffffu, d[2], o);
        d[3] += __shfl_xor_sync(0xffffffffu, d[3], o);
    }

    if (seg == 0){
        float mn = sqrtf(sq);
        size_t base = (size_t)b*HH*NN + row;
        #pragma unroll
        for (int h = 0; h < HH; h++)
            g_scores[base + (size_t)h*NN] = sb[h]*d[h]/(skn[h]*mn + 1e-8f);
    }
}

// ---------------- k2: softmax + interp + shift + sharpen ----------------
// 1024 threads, 8 contiguous elements per thread, float4 global I/O.
#define K2T 1024
#define VT  8
__device__ __forceinline__ float blk_reduce(float v, bool is_max, float* red, float* bc){
    int t = threadIdx.x, lane = t & 31, wid = t >> 5;
    #pragma unroll
    for (int o = 16; o; o >>= 1){
        float u = __shfl_xor_sync(0xffffffffu, v, o);
        v = is_max ? fmaxf(v, u) : (v + u);
    }
    __syncthreads();                 // protect red/bc from previous round
    if (lane == 0) red[wid] = v;
    __syncthreads();
    if (t == 0){
        float a = red[0];
        #pragma unroll
        for (int k = 1; k < K2T/32; k++) a = is_max ? fmaxf(a, red[k]) : (a + red[k]);
        *bc = a;
    }
    __syncthreads();
    return *bc;
}

__global__ __launch_bounds__(K2T) void k2_weights(const float* __restrict__ prev, int b0){
    int bh = b0*HH + blockIdx.x;     // chunk batches are contiguous
    __shared__ float sm[NN];
    __shared__ float red[K2T/32];
    __shared__ float bc;
    int t = threadIdx.x;

    const float* p = g_params + bh*8;
    float gate = p[1], s0 = p[2], s1 = p[3], s2 = p[4], gamma = p[5];

    const float* sc = g_scores + (size_t)bh*NN;
    const float* pr = prev     + (size_t)bh*NN;

    // front-batched loads: scores + prev (4 independent float4)
    float4 v0 = ((const float4*)sc)[t*2];
    float4 v1 = ((const float4*)sc)[t*2 + 1];
    float4 p0 = ((const float4*)pr)[t*2];
    float4 p1 = ((const float4*)pr)[t*2 + 1];

    float v[VT] = {v0.x, v0.y, v0.z, v0.w, v1.x, v1.y, v1.z, v1.w};
    float pv[VT] = {p0.x, p0.y, p0.z, p0.w, p1.x, p1.y, p1.z, p1.w};

    float lmax = v[0];
    #pragma unroll
    for (int j = 1; j < VT; j++) lmax = fmaxf(lmax, v[j]);
    float M = blk_reduce(lmax, true, red, &bc);

    float lsum = 0.f;
    #pragma unroll
    for (int j = 0; j < VT; j++){ v[j] = __expf(v[j] - M); lsum += v[j]; }
    float S = blk_reduce(lsum, false, red, &bc);
    float invS = 1.f / S;

    #pragma unroll
    for (int j = 0; j < VT; j++)
        sm[t*VT + j] = gate * (v[j] * invS) + (1.f - gate) * pv[j];
    __syncthreads();

    float ls = 0.f;
    #pragma unroll
    for (int j = 0; j < VT; j++){
        int n  = t*VT + j;
        int nm = (n + NN - 1) & (NN - 1);
        int np = (n + 1) & (NN - 1);
        float x = s0*sm[nm] + s1*sm[n] + s2*sm[np];
        float pw = __powf(x, gamma);
        v[j] = pw;
        ls += pw;
    }
    float T = blk_reduce(ls, false, red, &bc);
    float invT = 1.f / (T + 1e-8f);

    float* wout = g_w + (size_t)bh*NN;
    float4 o0 = {v[0]*invT, v[1]*invT, v[2]*invT, v[3]*invT};
    float4 o1 = {v[4]*invT, v[5]*invT, v[6]*invT, v[7]*invT};
    ((float4*)wout)[t*2]     = o0;
    ((float4*)wout)[t*2 + 1] = o1;
}

// ---------------- k3: erase/add update (chunked; mem read hits L2) ----------------
#define K3_ROWS 64
__global__ __launch_bounds__(256) void k3_out(const float* __restrict__ mem,
                                              float* __restrict__ out, int b0){
    int b  = b0 + blockIdx.y;
    int n0 = blockIdx.x * K3_ROWS;
    __shared__ float se[HH][WW], sv[HH][WW];
    __shared__ float sa[HH][K3_ROWS];
    int t = threadIdx.x;
    se[t >> 6][t & 63] = g_erase[b*HH*WW + t];
    sv[t >> 6][t & 63] = g_wvec [b*HH*WW + t];
    {   // preload the 4x64 weight tile (coalesced, one element per thread)
        int h = t >> 6, r = t & 63;
        sa[h][r] = g_w[((size_t)b*HH + h)*NN + n0 + r];
    }
    __syncthreads();

    int lane = t & 15, r = t >> 4;
    // head constants resident in registers (R3 layout — no reg cap)
    float4 e0 = ((const float4*)se[0])[lane];
    float4 e1 = ((const float4*)se[1])[lane];
    float4 e2 = ((const float4*)se[2])[lane];
    float4 e3 = ((const float4*)se[3])[lane];
    float4 w0 = ((const float4*)sv[0])[lane];
    float4 w1 = ((const float4*)sv[1])[lane];
    float4 w2 = ((const float4*)sv[2])[lane];
    float4 w3 = ((const float4*)sv[3])[lane];

    #pragma unroll
    for (int i = 0; i < K3_ROWS/16; i++){
        int rr = r + 16*i;
        float a0 = sa[0][rr], a1 = sa[1][rr], a2 = sa[2][rr], a3 = sa[3][rr];
        size_t idx = ((size_t)b*NN + n0 + rr)*16 + lane;
        float4 m = __ldcs((const float4*)mem + idx);   // evict-first: no reuse
        float4 o;
        o.x = m.x*(1.f-a0*e0.x)*(1.f-a1*e1.x)*(1.f-a2*e2.x)*(1.f-a3*e3.x)
            + a0*w0.x + a1*w1.x + a2*w2.x + a3*w3.x;
        o.y = m.y*(1.f-a0*e0.y)*(1.f-a1*e1.y)*(1.f-a2*e2.y)*(1.f-a3*e3.y)
            + a0*w0.y + a1*w1.y + a2*w2.y + a3*w3.y;
        o.z = m.z*(1.f-a0*e0.z)*(1.f-a1*e1.z)*(1.f-a2*e2.z)*(1.f-a3*e3.z)
            + a0*w0.z + a1*w1.z + a2*w2.z + a3*w3.z;
        o.w = m.w*(1.f-a0*e0.w)*(1.f-a1*e1.w)*(1.f-a2*e2.w)*(1.f-a3*e3.w)
            + a0*w0.w + a1*w1.w + a2*w2.w + a3*w3.w;
        __stcs((float4*)out + idx, o);                 // don't pollute L2
    }
}

// ---------------- launch: chunked pipeline for L2 reuse ----------------
extern "C" void kernel_launch(void* const* d_in, const int* in_sizes, int n_in,
                              void* d_out, int out_size) {
    const float* mem  = (const float*)d_in[0];   // [B,N,W]
    const float* ctrl = (const float*)d_in[1];   // [B,792]
    const float* prev = (const float*)d_in[2];   // [B,H,N]
    float* out = (float*)d_out;                  // [B,N,W]

    k0_controls<<<BB*HH, 64>>>(ctrl);
    for (int c = 0; c < NC; c++){
        int b0 = c * CB;
        k1_scores  <<<dim3(NN/K1_ROWSPB, CB), 256>>>(mem, b0);
        k2_weights <<<CB*HH, K2T>>>(prev, b0);
        k3_out     <<<dim3(NN/K3_ROWS, CB), 256>>>(mem, out, b0);
    }
    (void)in_sizes; (void)n_in; (void)out_size;
}

// round 7
// speedup vs baseline: 1.6680x; 1.6680x over previous
#include <cuda_runtime.h>
#include <math.h>

#define BB 64
#define NN 8192
#define WW 64
#define HH 4
#define CTRL 792   // H*(3W+6)

// ---------------- scratch (no allocation allowed) ----------------
__device__ float g_keys [BB*HH*WW];   // tanh(keys)
__device__ float g_erase[BB*HH*WW];   // sigmoid(erase)
__device__ float g_wvec [BB*HH*WW];   // tanh(write)
__device__ float g_params[BB*HH*8];   // beta,gate,s0,s1,s2,gamma,keynorm
__device__ float g_scores[(size_t)BB*HH*NN];  // beta * cosine
__device__ float g_w     [(size_t)BB*HH*NN];  // final write distribution

__device__ __forceinline__ float softplusf(float x){
    return x > 20.f ? x : log1pf(expf(x));
}
__device__ __forceinline__ float sigmoidf(float x){
    return 1.f/(1.f + expf(-x));
}

// ---------------- k0: control transforms (tiny) ----------------
__global__ void k0_controls(const float* __restrict__ ctrl){
    int bh = blockIdx.x;                 // b*4+h
    int b  = bh >> 2, h = bh & 3;
    int t  = threadIdx.x;                // 64 threads
    const float* c = ctrl + b*CTRL;

    float k = tanhf(c[h*WW + t]);
    g_keys [bh*WW + t] = k;
    g_erase[bh*WW + t] = sigmoidf(c[256 + h*WW + t]);
    g_wvec [bh*WW + t] = tanhf(c[512 + h*WW + t]);

    __shared__ float s2[2];
    float sq = k*k;
    #pragma unroll
    for (int o = 16; o; o >>= 1) sq += __shfl_xor_sync(0xffffffffu, sq, o);
    if ((t & 31) == 0) s2[t >> 5] = sq;
    __syncthreads();
    if (t == 0){
        float nrm   = sqrtf(s2[0] + s2[1]);
        float beta  = softplusf(c[768 + h]);
        float gate  = sigmoidf(c[772 + h]);
        float gamma = 1.f + softplusf(c[788 + h]);
        float a0 = c[776 + h*3 + 0], a1 = c[776 + h*3 + 1], a2 = c[776 + h*3 + 2];
        float m  = fmaxf(a0, fmaxf(a1, a2));
        float e0 = expf(a0 - m), e1 = expf(a1 - m), e2 = expf(a2 - m);
        float inv = 1.f/(e0 + e1 + e2);
        float* p = g_params + bh*8;
        p[0]=beta; p[1]=gate; p[2]=e0*inv; p[3]=e1*inv; p[4]=e2*inv; p[5]=gamma; p[6]=nrm;
    }
}

// ---------------- k1: beta * cosine scores (full batch) ----------------
// 4 lanes per memory row, 16 floats (4 float4) per lane, 2 shuffle rounds.
#define K1_ROWSPB 64
__global__ __launch_bounds__(256) void k1_scores(const float* __restrict__ mem){
    int b  = blockIdx.y;
    int n0 = blockIdx.x * K1_ROWSPB;
    __shared__ float skey[HH*WW];
    __shared__ float sb[HH], skn[HH];
    int t = threadIdx.x;
    skey[t] = g_keys[b*HH*WW + t];
    if (t < HH){ sb[t] = g_params[(b*HH + t)*8 + 0]; skn[t] = g_params[(b*HH + t)*8 + 6]; }
    __syncthreads();

    int seg = t & 3;            // which 16-float segment of W
    int row = n0 + (t >> 2);    // one memory row per thread

    const float4* mrow = (const float4*)(mem + ((size_t)b*NN + row)*WW) + seg*4;
    float4 m0 = mrow[0], m1 = mrow[1], m2 = mrow[2], m3 = mrow[3];

    float sq = m0.x*m0.x + m0.y*m0.y + m0.z*m0.z + m0.w*m0.w
             + m1.x*m1.x + m1.y*m1.y + m1.z*m1.z + m1.w*m1.w
             + m2.x*m2.x + m2.y*m2.y + m2.z*m2.z + m2.w*m2.w
             + m3.x*m3.x + m3.y*m3.y + m3.z*m3.z + m3.w*m3.w;

    float d[HH];
    #pragma unroll
    for (int h = 0; h < HH; h++){
        const float4* kp = (const float4*)(skey + h*WW) + seg*4;
        float4 k0 = kp[0], k1 = kp[1], k2 = kp[2], k3 = kp[3];
        d[h] = m0.x*k0.x + m0.y*k0.y + m0.z*k0.z + m0.w*k0.w
             + m1.x*k1.x + m1.y*k1.y + m1.z*k1.z + m1.w*k1.w
             + m2.x*k2.x + m2.y*k2.y + m2.z*k2.z + m2.w*k2.w
             + m3.x*k3.x + m3.y*k3.y + m3.z*k3.z + m3.w*k3.w;
    }

    #pragma unroll
    for (int o = 1; o <= 2; o <<= 1){
        sq   += __shfl_xor_sync(0xffffffffu, sq,   o);
        d[0] += __shfl_xor_sync(0xffffffffu, d[0], o);
        d[1] += __shfl_xor_sync(0xffffffffu, d[1], o);
        d[2] += __shfl_xor_sync(0xffffffffu, d[2], o);
        d[3] += __shfl_xor_sync(0xffffffffu, d[3], o);
    }

    if (seg == 0){
        float mn = sqrtf(sq);
        size_t base = (size_t)b*HH*NN + row;
        #pragma unroll
        for (int h = 0; h < HH; h++)
            g_scores[base + (size_t)h*NN] = sb[h]*d[h]/(skn[h]*mn + 1e-8f);
    }
}

// ---------------- k2: softmax + interp + shift + sharpen ----------------
// full batch: 256 blocks of 1024 threads, 8 contiguous elems/thread, float4 I/O.
#define K2T 1024
#define VT  8
__device__ __forceinline__ float blk_reduce(float v, bool is_max, float* red, float* bc){
    int t = threadIdx.x, lane = t & 31, wid = t >> 5;
    #pragma unroll
    for (int o = 16; o; o >>= 1){
        float u = __shfl_xor_sync(0xffffffffu, v, o);
        v = is_max ? fmaxf(v, u) : (v + u);
    }
    __syncthreads();                 // protect red/bc from previous round
    if (lane == 0) red[wid] = v;
    __syncthreads();
    if (t == 0){
        float a = red[0];
        #pragma unroll
        for (int k = 1; k < K2T/32; k++) a = is_max ? fmaxf(a, red[k]) : (a + red[k]);
        *bc = a;
    }
    __syncthreads();
    return *bc;
}

__global__ __launch_bounds__(K2T) void k2_weights(const float* __restrict__ prev){
    int bh = blockIdx.x;
    __shared__ float sm[NN];
    __shared__ float red[K2T/32];
    __shared__ float bc;
    int t = threadIdx.x;

    const float* p = g_params + bh*8;
    float gate = p[1], s0 = p[2], s1 = p[3], s2 = p[4], gamma = p[5];

    const float* sc = g_scores + (size_t)bh*NN;
    const float* pr = prev     + (size_t)bh*NN;

    // front-batched loads: scores + prev (4 independent float4)
    float4 v0 = ((const float4*)sc)[t*2];
    float4 v1 = ((const float4*)sc)[t*2 + 1];
    float4 p0 = ((const float4*)pr)[t*2];
    float4 p1 = ((const float4*)pr)[t*2 + 1];

    float v[VT] = {v0.x, v0.y, v0.z, v0.w, v1.x, v1.y, v1.z, v1.w};
    float pv[VT] = {p0.x, p0.y, p0.z, p0.w, p1.x, p1.y, p1.z, p1.w};

    float lmax = v[0];
    #pragma unroll
    for (int j = 1; j < VT; j++) lmax = fmaxf(lmax, v[j]);
    float M = blk_reduce(lmax, true, red, &bc);

    float lsum = 0.f;
    #pragma unroll
    for (int j = 0; j < VT; j++){ v[j] = __expf(v[j] - M); lsum += v[j]; }
    float S = blk_reduce(lsum, false, red, &bc);
    float invS = 1.f / S;

    #pragma unroll
    for (int j = 0; j < VT; j++)
        sm[t*VT + j] = gate * (v[j] * invS) + (1.f - gate) * pv[j];
    __syncthreads();

    float ls = 0.f;
    #pragma unroll
    for (int j = 0; j < VT; j++){
        int n  = t*VT + j;
        int nm = (n + NN - 1) & (NN - 1);
        int np = (n + 1) & (NN - 1);
        float x = s0*sm[nm] + s1*sm[n] + s2*sm[np];
        float pw = __powf(x, gamma);
        v[j] = pw;
        ls += pw;
    }
    float T = blk_reduce(ls, false, red, &bc);
    float invT = 1.f / (T + 1e-8f);

    float* wout = g_w + (size_t)bh*NN;
    float4 o0 = {v[0]*invT, v[1]*invT, v[2]*invT, v[3]*invT};
    float4 o1 = {v[4]*invT, v[5]*invT, v[6]*invT, v[7]*invT};
    ((float4*)wout)[t*2]     = o0;
    ((float4*)wout)[t*2 + 1] = o1;
}

// ---------------- k3: erase/add update, MLP=8 front-batched ----------------
#define K3_ROWS 128
__global__ __launch_bounds__(256) void k3_out(const float* __restrict__ mem,
                                              float* __restrict__ out){
    int b  = blockIdx.y;
    int n0 = blockIdx.x * K3_ROWS;
    __shared__ float se[HH][WW], sv[HH][WW];
    __shared__ float sa[HH][K3_ROWS];
    int t = threadIdx.x;
    se[t >> 6][t & 63] = g_erase[b*HH*WW + t];
    sv[t >> 6][t & 63] = g_wvec [b*HH*WW + t];
    {   // coalesced preload of the 4x128 weight tile (2 per thread)
        int i0 = t, i1 = t + 256;
        sa[i0 >> 7][i0 & 127] = g_w[((size_t)b*HH + (i0 >> 7))*NN + n0 + (i0 & 127)];
        sa[i1 >> 7][i1 & 127] = g_w[((size_t)b*HH + (i1 >> 7))*NN + n0 + (i1 & 127)];
    }
    __syncthreads();

    int lane = t & 15, r = t >> 4;
    // head constants resident in registers
    float4 e0 = ((const float4*)se[0])[lane];
    float4 e1 = ((const float4*)se[1])[lane];
    float4 e2 = ((const float4*)se[2])[lane];
    float4 e3 = ((const float4*)se[3])[lane];
    float4 w0 = ((const float4*)sv[0])[lane];
    float4 w1 = ((const float4*)sv[1])[lane];
    float4 w2 = ((const float4*)sv[2])[lane];
    float4 w3 = ((const float4*)sv[3])[lane];

    size_t base = ((size_t)b*NN + n0 + r)*16 + lane;

    // front-batch 8 independent 16B loads (MLP=8)
    float4 m[8];
    #pragma unroll
    for (int i = 0; i < 8; i++)
        m[i] = __ldcs((const float4*)mem + base + (size_t)16*16*i);

    #pragma unroll
    for (int i = 0; i < 8; i++){
        int rr = r + 16*i;
        float a0 = sa[0][rr], a1 = sa[1][rr], a2 = sa[2][rr], a3 = sa[3][rr];
        float4 o;
        o.x = m[i].x*(1.f-a0*e0.x)*(1.f-a1*e1.x)*(1.f-a2*e2.x)*(1.f-a3*e3.x)
            + a0*w0.x + a1*w1.x + a2*w2.x + a3*w3.x;
        o.y = m[i].y*(1.f-a0*e0.y)*(1.f-a1*e1.y)*(1.f-a2*e2.y)*(1.f-a3*e3.y)
            + a0*w0.y + a1*w1.y + a2*w2.y + a3*w3.y;
        o.z = m[i].z*(1.f-a0*e0.z)*(1.f-a1*e1.z)*(1.f-a2*e2.z)*(1.f-a3*e3.z)
            + a0*w0.z + a1*w1.z + a2*w2.z + a3*w3.z;
        o.w = m[i].w*(1.f-a0*e0.w)*(1.f-a1*e1.w)*(1.f-a2*e2.w)*(1.f-a3*e3.w)
            + a0*w0.w + a1*w1.w + a2*w2.w + a3*w3.w;
        __stcs((float4*)out + base + (size_t)16*16*i, o);
    }
}

// ---------------- launch ----------------
extern "C" void kernel_launch(void* const* d_in, const int* in_sizes, int n_in,
                              void* d_out, int out_size) {
    const float* mem  = (const float*)d_in[0];   // [B,N,W]
    const float* ctrl = (const float*)d_in[1];   // [B,792]
    const float* prev = (const float*)d_in[2];   // [B,H,N]
    float* out = (float*)d_out;                  // [B,N,W]

    k0_controls<<<BB*HH, 64>>>(ctrl);
    k1_scores  <<<dim3(NN/K1_ROWSPB, BB), 256>>>(mem);
    k2_weights <<<BB*HH, K2T>>>(prev);
    k3_out     <<<dim3(NN/K3_ROWS, BB), 256>>>(mem, out);
    (void)in_sizes; (void)n_in; (void)out_size;
}